// round 1
// baseline (speedup 1.0000x reference)
#include <cuda_runtime.h>
#include <cstdint>

// ---------------- scratch (static __device__ arrays; no allocations) ----------------
__device__ float g_pool1[512*16*12*36*3];   // 42.5 MB
__device__ float g_pool2[512*32*6*18*3];    // 21.2 MB
__device__ float g_flat [512*64*81];        // 10.6 MB  (B, D,H,W,C) layout
__device__ float g_mean [512*64];

// ---------------- fused conv3d(3x3x3,pad1) + relu + maxpool(2,2,1) ----------------
// One thread computes output (b, oc0..oc0+NOC-1, dp, hp, w=0..2):
// 12 conv values per oc (2d x 2h x 3w) pooled to 3 outputs.
template<int IC, int DIN, int HIN, int OCT, int NOC, bool FLAT>
__global__ __launch_bounds__(432, 1)
void convpool_kernel(const float* __restrict__ in,
                     const float* __restrict__ wgt,
                     const float* __restrict__ bias,
                     float* __restrict__ out)
{
    constexpr int DOUT = DIN/2, HOUT = HIN/2;
    const int hp  = threadIdx.x;
    const int dp  = threadIdx.y;
    const int oc0 = (blockIdx.y * blockDim.z + threadIdx.z) * NOC;
    const int b   = blockIdx.x;

    float acc[NOC][12];
    #pragma unroll
    for (int o = 0; o < NOC; o++)
        #pragma unroll
        for (int j = 0; j < 12; j++) acc[o][j] = 0.f;

    const float* inb = in + (size_t)b * IC * DIN * HIN * 3;

    #pragma unroll 1
    for (int ic = 0; ic < IC; ++ic) {
        float p[4][4][3];
        const float* inc = inb + (size_t)ic * (DIN*HIN*3);
        #pragma unroll
        for (int di = 0; di < 4; ++di) {
            int d = 2*dp - 1 + di;
            bool okd = (unsigned)d < (unsigned)DIN;
            #pragma unroll
            for (int hi = 0; hi < 4; ++hi) {
                int h = 2*hp - 1 + hi;
                bool ok = okd && ((unsigned)h < (unsigned)HIN);
                const float* rowp = inc + ((size_t)d * HIN + h) * 3;
                p[di][hi][0] = ok ? __ldg(rowp + 0) : 0.f;
                p[di][hi][1] = ok ? __ldg(rowp + 1) : 0.f;
                p[di][hi][2] = ok ? __ldg(rowp + 2) : 0.f;
            }
        }
        #pragma unroll
        for (int o = 0; o < NOC; o++) {
            const float* wb = wgt + ((size_t)(oc0 + o) * IC + ic) * 27;
            #pragma unroll
            for (int kd = 0; kd < 3; kd++)
            #pragma unroll
            for (int kh = 0; kh < 3; kh++)
            #pragma unroll
            for (int kw = 0; kw < 3; kw++) {
                float wv = __ldg(wb + (kd*3 + kh)*3 + kw);
                #pragma unroll
                for (int dd = 0; dd < 2; dd++)
                #pragma unroll
                for (int hh = 0; hh < 2; hh++)
                #pragma unroll
                for (int w = 0; w < 3; w++) {
                    int iw = w + kw - 1;
                    if (iw >= 0 && iw < 3)
                        acc[o][(dd*2 + hh)*3 + w] += wv * p[dd + kd][hh + kh][iw];
                }
            }
        }
    }

    #pragma unroll
    for (int o = 0; o < NOC; o++) {
        float bv = __ldg(bias + oc0 + o);
        #pragma unroll
        for (int w = 0; w < 3; w++) {
            float v = acc[o][0*3 + w];
            v = fmaxf(v, acc[o][1*3 + w]);
            v = fmaxf(v, acc[o][2*3 + w]);
            v = fmaxf(v, acc[o][3*3 + w]);
            v = fmaxf(v + bv, 0.f);
            if (FLAT) {
                // (B, D, H, W, C) layout for the reshape/flatten path
                out[(size_t)b * (DOUT*HOUT*3*OCT) + (((dp*HOUT) + hp)*3 + w) * OCT + (oc0 + o)] = v;
            } else {
                out[(((size_t)b * OCT + oc0 + o) * DOUT + dp) * (HOUT*3) + hp*3 + w] = v;
            }
        }
    }
}

// ---------------- mean over the 81 spatial positions ----------------
__global__ void mean_kernel()
{
    int b = blockIdx.x, c = threadIdx.x;
    const float* f = g_flat + (size_t)b * 5184 + c;
    float s = 0.f;
    #pragma unroll
    for (int p = 0; p < 81; p++) s += f[p * 64];
    g_mean[b * 64 + c] = s * (1.f / 81.f);
}

// ---------------- smem-tiled matvec: out[n=t][r=0..3] += W[n][k] * X[k][r] ----------------
// W: global row-major [256][K].  Xsh: smem [K][4] (float4-aligned rows).
// Wsh: smem staging tile [256][KT+4].  256 threads required.
template<int K, int KT>
__device__ __forceinline__ void matvec4(const float* __restrict__ W,
                                        const float* __restrict__ Xsh,
                                        float* __restrict__ Wsh,
                                        float acc[4], int t)
{
    constexpr int RS = KT + 4;   // padded row stride (floats), 16B multiple
    constexpr int QP = KT / 4;   // float4 quads per row per tile
    for (int kt = 0; kt < K; kt += KT) {
        __syncthreads();
        #pragma unroll
        for (int i = 0; i < QP; i++) {
            int idx = t + i * 256;
            int n   = idx / QP;
            int kq  = idx % QP;
            float4 v = *(const float4*)(W + (size_t)n * K + kt + kq * 4);
            *(float4*)(Wsh + n * RS + kq * 4) = v;
        }
        __syncthreads();
        #pragma unroll
        for (int kk = 0; kk < KT; kk += 4) {
            float4 wv = *(const float4*)(Wsh + t * RS + kk);
            float4 x0 = *(const float4*)(Xsh + (kt + kk + 0) * 4);
            float4 x1 = *(const float4*)(Xsh + (kt + kk + 1) * 4);
            float4 x2 = *(const float4*)(Xsh + (kt + kk + 2) * 4);
            float4 x3 = *(const float4*)(Xsh + (kt + kk + 3) * 4);
            acc[0] += wv.x * x0.x; acc[1] += wv.x * x0.y; acc[2] += wv.x * x0.z; acc[3] += wv.x * x0.w;
            acc[0] += wv.y * x1.x; acc[1] += wv.y * x1.y; acc[2] += wv.y * x1.z; acc[3] += wv.y * x1.w;
            acc[0] += wv.z * x2.x; acc[1] += wv.z * x2.y; acc[2] += wv.z * x2.z; acc[3] += wv.z * x2.w;
            acc[0] += wv.w * x3.x; acc[1] += wv.w * x3.y; acc[2] += wv.w * x3.z; acc[3] += wv.w * x3.w;
        }
    }
}

// ---------------- RNN decoder: 128 blocks x 4 batch rows, fully independent ----------------
__global__ __launch_bounds__(256, 1)
void rnn_kernel(const float* __restrict__ whh1, const float* __restrict__ wih2,
                const float* __restrict__ whh2,
                const float* __restrict__ w_init_h,  const float* __restrict__ b_init_h,
                const float* __restrict__ w_init_h2, const float* __restrict__ b_init_h2,
                const float* __restrict__ wih1, const float* __restrict__ bih1,
                const float* __restrict__ bhh1,
                const float* __restrict__ bih2, const float* __restrict__ bhh2,
                const float* __restrict__ w_fc, const float* __restrict__ b_fc,
                float* __restrict__ preds)
{
    extern __shared__ float sm[];
    float* me   = sm;            //  64*4 = 256
    float* hS   = sm + 256;      // 256*4 = 1024
    float* h2S  = sm + 1280;
    float* ihcS = sm + 2304;
    float* hnS  = sm + 3328;
    float* Wsh  = sm + 4352;     // 256*36 = 9216  -> total 13568 floats = 54272 B

    const int t  = threadIdx.x;
    const int r0 = blockIdx.x * 4;

    { int r = t & 3, k = t >> 2;
      me[k*4 + r] = g_mean[(size_t)(r0 + r) * 64 + k]; }

    float a[4] = {0,0,0,0};
    matvec4<64,32>(w_init_h, me, Wsh, a, t);
    float c[4] = {0,0,0,0};
    matvec4<64,32>(wih1, me, Wsh, c, t);
    {
        float bh = __ldg(b_init_h + t);
        float bi = __ldg(bih1 + t) + __ldg(bhh1 + t);
        #pragma unroll
        for (int r = 0; r < 4; r++) { hS[t*4 + r] = a[r] + bh; ihcS[t*4 + r] = c[r] + bi; }
    }
    float a2[4] = {0,0,0,0};
    matvec4<256,32>(w_init_h2, hS, Wsh, a2, t);
    {
        float b2 = __ldg(b_init_h2 + t);
        #pragma unroll
        for (int r = 0; r < 4; r++) h2S[t*4 + r] = a2[r] + b2;
    }
    const float bi2 = __ldg(bih2 + t) + __ldg(bhh2 + t);
    const float bfc = __ldg(b_fc);

    for (int step = 0; step < 23; ++step) {
        float ah[4] = {0,0,0,0};
        matvec4<256,32>(whh1, hS, Wsh, ah, t);           // internal sync orders prior smem writes
        #pragma unroll
        for (int r = 0; r < 4; r++) hnS[t*4 + r] = tanhf(ihcS[t*4 + r] + ah[r]);
        float u[4] = {0,0,0,0};
        matvec4<256,32>(wih2, hnS, Wsh, u, t);
        float v[4] = {0,0,0,0};
        matvec4<256,32>(whh2, h2S, Wsh, v, t);
        __syncthreads();                                  // all reads of hS/h2S/hnS done
        #pragma unroll
        for (int r = 0; r < 4; r++) {
            h2S[t*4 + r] = tanhf(u[r] + v[r] + bi2);
            hS[t*4 + r]  = hnS[t*4 + r];
        }
        __syncthreads();
        if (t < 128) {                                    // pred: one warp per batch row
            int r = t >> 5, lane = t & 31;
            float s = 0.f;
            #pragma unroll
            for (int k = lane; k < 256; k += 32) s += __ldg(w_fc + k) * h2S[k*4 + r];
            #pragma unroll
            for (int off = 16; off; off >>= 1) s += __shfl_down_sync(0xffffffffu, s, off);
            if (lane == 0) preds[(size_t)(r0 + r) * 23 + step] = s + bfc;
        }
    }
}

// ---------------- linear head: tanh(flat @ w_lin1^T + b) @ w_lin2^T + b ----------------
__global__ __launch_bounds__(256, 1)
void head_kernel(const float* __restrict__ w_lin1, const float* __restrict__ b_lin1,
                 const float* __restrict__ w_lin2, const float* __restrict__ b_lin2,
                 float* __restrict__ outc)
{
    extern __shared__ float sm[];
    float* xS  = sm;             // 5184*4 = 20736
    float* thS = sm + 20736;     // 1024
    float* Wsh = sm + 21760;     // 256*68 = 17408 -> total 39168 floats = 156672 B
    const int t  = threadIdx.x;
    const int r0 = blockIdx.x * 4;

    for (int idx = t; idx < 4 * 5184; idx += 256) {
        int r = idx / 5184, k = idx % 5184;
        xS[k*4 + r] = g_flat[(size_t)(r0 + r) * 5184 + k];
    }

    float a[4] = {0,0,0,0};
    matvec4<5184,64>(w_lin1, xS, Wsh, a, t);
    float bl = __ldg(b_lin1 + t);
    #pragma unroll
    for (int r = 0; r < 4; r++) thS[t*4 + r] = tanhf(a[r] + bl);
    __syncthreads();

    if (t < 48) {
        int n = t % 12, r = t / 12;
        float s = 0.f;
        #pragma unroll 4
        for (int k = 0; k < 256; k++) s += __ldg(w_lin2 + n*256 + k) * thS[k*4 + r];
        outc[(size_t)(r0 + r) * 12 + n] = s + __ldg(b_lin2 + n);
    }
}

// ---------------- launch ----------------
extern "C" void kernel_launch(void* const* d_in, const int* in_sizes, int n_in,
                              void* d_out, int out_size)
{
    const float* x    = (const float*)d_in[0];
    const float* w1   = (const float*)d_in[1];
    const float* b1   = (const float*)d_in[2];
    const float* w2   = (const float*)d_in[3];
    const float* b2   = (const float*)d_in[4];
    const float* w3   = (const float*)d_in[5];
    const float* b3   = (const float*)d_in[6];
    const float* wih1 = (const float*)d_in[7];
    const float* whh1 = (const float*)d_in[8];
    const float* bih1 = (const float*)d_in[9];
    const float* bhh1 = (const float*)d_in[10];
    const float* wih2 = (const float*)d_in[11];
    const float* whh2 = (const float*)d_in[12];
    const float* bih2 = (const float*)d_in[13];
    const float* bhh2 = (const float*)d_in[14];
    const float* w_init_h  = (const float*)d_in[15];
    const float* b_init_h  = (const float*)d_in[16];
    const float* w_init_h2 = (const float*)d_in[17];
    const float* b_init_h2 = (const float*)d_in[18];
    const float* w_fc  = (const float*)d_in[19];
    const float* b_fc  = (const float*)d_in[20];
    const float* w_lin1 = (const float*)d_in[21];
    const float* b_lin1 = (const float*)d_in[22];
    const float* w_lin2 = (const float*)d_in[23];
    const float* b_lin2 = (const float*)d_in[24];
    float* out = (float*)d_out;

    float *p1, *p2, *pf;
    cudaGetSymbolAddress((void**)&p1, g_pool1);
    cudaGetSymbolAddress((void**)&p2, g_pool2);
    cudaGetSymbolAddress((void**)&pf, g_flat);

    // stage 1: (512,6,24,72,3) -> (512,16,12,36,3)
    convpool_kernel<6, 24, 72, 16, 4, false>
        <<<dim3(512, 4), dim3(36, 12, 1)>>>(x, w1, b1, p1);
    // stage 2: -> (512,32,6,18,3)
    convpool_kernel<16, 12, 36, 32, 4, false>
        <<<dim3(512, 2), dim3(18, 6, 4)>>>(p1, w2, b2, p2);
    // stage 3: -> (512, 3,9,3, 64) flat layout
    convpool_kernel<32, 6, 18, 64, 4, true>
        <<<dim3(512, 1), dim3(9, 3, 16)>>>(p2, w3, b3, pf);

    mean_kernel<<<512, 64>>>();

    cudaFuncSetAttribute(rnn_kernel, cudaFuncAttributeMaxDynamicSharedMemorySize, 54272);
    rnn_kernel<<<128, 256, 54272>>>(whh1, wih2, whh2,
                                    w_init_h, b_init_h, w_init_h2, b_init_h2,
                                    wih1, bih1, bhh1, bih2, bhh2,
                                    w_fc, b_fc, out /* predictions: first 512*23 floats */);

    cudaFuncSetAttribute(head_kernel, cudaFuncAttributeMaxDynamicSharedMemorySize, 156672);
    head_kernel<<<128, 256, 156672>>>(w_lin1, b_lin1, w_lin2, b_lin2,
                                      out + 512 * 23 /* out_c region */);
}